// round 16
// baseline (speedup 1.0000x reference)
#include <cuda_runtime.h>
#include <cuda_fp16.h>
#include <cstdint>

#define B_  4
#define L_  1024
#define H_  1024
#define NH_ 16
#define HD_ 64
#define M_  (B_*L_)   // 4096
#define NP_ (5 * H_)  // fused projection width 5120
#define LOG2E 1.4426950408889634f

// ---------------- scratch ----------------
__device__ __half g_xh  [M_ * H_];
__device__ __half g_proj[M_ * NP_];          // [Q(scaled) | Ks | Vs | Kl | Vl]
__device__ __half g_mixh[M_ * H_];           // atomically mixed attention output
__device__ __half g_Wall[NP_ * H_];          // [Wq^T*qs ; Wkvs^T ; Wkvl^T]
__device__ __half g_Woth[H_ * H_];           // Wo^T

// ---------------- PTX helpers ----------------
__device__ __forceinline__ float ex2(float x) {
    float y; asm("ex2.approx.ftz.f32 %0, %1;" : "=f"(y) : "f"(x)); return y;
}
__device__ __forceinline__ void mma_f16(float* d, const uint32_t* a,
                                        uint32_t b0, uint32_t b1) {
    asm volatile(
        "mma.sync.aligned.m16n8k16.row.col.f32.f16.f16.f32 "
        "{%0,%1,%2,%3}, {%4,%5,%6,%7}, {%8,%9}, {%0,%1,%2,%3};"
        : "+f"(d[0]), "+f"(d[1]), "+f"(d[2]), "+f"(d[3])
        : "r"(a[0]), "r"(a[1]), "r"(a[2]), "r"(a[3]), "r"(b0), "r"(b1));
}
__device__ __forceinline__ void ldsm4(uint32_t* r, uint32_t addr) {
    asm volatile("ldmatrix.sync.aligned.m8n8.x4.shared.b16 {%0,%1,%2,%3}, [%4];"
        : "=r"(r[0]), "=r"(r[1]), "=r"(r[2]), "=r"(r[3]) : "r"(addr));
}
__device__ __forceinline__ void ldsm4t(uint32_t* r, uint32_t addr) {
    asm volatile("ldmatrix.sync.aligned.m8n8.x4.trans.shared.b16 {%0,%1,%2,%3}, [%4];"
        : "=r"(r[0]), "=r"(r[1]), "=r"(r[2]), "=r"(r[3]) : "r"(addr));
}
__device__ __forceinline__ void cp16(void* smem_dst, const void* gmem_src) {
    unsigned s = (unsigned)__cvta_generic_to_shared(smem_dst);
    asm volatile("cp.async.cg.shared.global [%0], [%1], 16;" :: "r"(s), "l"(gmem_src));
}
__device__ __forceinline__ uint32_t smem_u32(const void* p) {
    uint32_t a;
    asm("{ .reg .u64 t; cvta.to.shared.u64 t, %1; cvt.u32.u64 %0, t; }" : "=r"(a) : "l"(p));
    return a;
}
__device__ __forceinline__ uint32_t packh2(float a, float b) {
    uint32_t r;
    asm("cvt.rn.f16x2.f32 %0, %2, %1;" : "=r"(r) : "f"(a), "f"(b));
    return r;
}
__device__ __forceinline__ void red_h2(__half* p, uint32_t v) {
    asm volatile("red.global.add.noftz.f16x2 [%0], %1;" :: "l"(p), "r"(v) : "memory");
}
#define GSW(o) ((o) ^ (((o) >> 3) & 0x70))

// ---------------- preprocessing ----------------
__global__ __launch_bounds__(256) void to_half(
    const float* __restrict__ src, __half* __restrict__ dst, int n4)
{
    int i = blockIdx.x * blockDim.x + threadIdx.x;
    if (i >= n4) return;
    float4 v = ((const float4*)src)[i];
    ((__half2*)dst)[2 * i]     = __floats2half2_rn(v.x, v.y);
    ((__half2*)dst)[2 * i + 1] = __floats2half2_rn(v.z, v.w);
}

__global__ __launch_bounds__(256) void zero_h(float4* __restrict__ p, int n)
{
    int i = blockIdx.x * blockDim.x + threadIdx.x;
    if (i < n) p[i] = make_float4(0.f, 0.f, 0.f, 0.f);
}

// weights: z=0..2 -> g_Wall (Wq^T*qscale ; Wkvs^T ; Wkvl^T), z=3 -> g_Woth
__global__ __launch_bounds__(256) void wtrans_h(
    const float* __restrict__ Wq, const float* __restrict__ Ws,
    const float* __restrict__ Wl, const float* __restrict__ Wo,
    __half* __restrict__ Wall, __half* __restrict__ Woth)
{
    const int z = blockIdx.z;
    const float* W = (z == 0) ? Wq : (z == 1) ? Ws : (z == 2) ? Wl : Wo;
    const int N = (z == 1 || z == 2) ? 2 * H_ : H_;
    const int n0 = blockIdx.x * 32, k0 = blockIdx.y * 32;
    if (n0 >= N) return;
    __shared__ float ts[32][33];
    const int tx = threadIdx.x, ty = threadIdx.y;
#pragma unroll
    for (int i = 0; i < 4; i++)
        ts[ty + 8 * i][tx] = W[(size_t)(k0 + ty + 8 * i) * N + n0 + tx];
    __syncthreads();
    const int rowOff = (z == 0) ? 0 : (z == 1) ? H_ : (z == 2) ? 3 * H_ : 0;
    const float sc = (z == 0) ? 0.125f * LOG2E : 1.0f;
    __half* T = (z == 3) ? Woth : (Wall + (size_t)rowOff * H_);
#pragma unroll
    for (int i = 0; i < 4; i++)
        T[(size_t)(n0 + ty + 8 * i) * H_ + k0 + tx] =
            __float2half_rn(ts[tx][ty + 8 * i] * sc);
}

// ---- projection GEMM: CTA 128x256, 8 warps (2x4), warp tile 64x64, 2-stage ----
#define GPSTG 49152                 // A 16KB + B 32KB per stage
#define GP_SMEM (2 * GPSTG)         // 98304

template<int K>
__global__ __launch_bounds__(256, 1) void gemm_p(
    const __half* __restrict__ A, const __half* __restrict__ Bm,
    __half* __restrict__ C, int M, int N)
{
    extern __shared__ char smem[];
    const uint32_t sb = smem_u32(smem);
    const int tid = threadIdx.x, lane = tid & 31, wid = tid >> 5;
    const int bm = blockIdx.y * 128, bn = blockIdx.x * 256;
    const int wm = (wid & 1) * 64, wn = (wid >> 1) * 64;

    // A loads: 2 threads/row, 4 chunks each. B loads: 1 thread/row, 8 chunks.
    const int arow = tid >> 1, ac0 = (tid & 1) * 4;
    const __half* Ag = A + (size_t)(bm + arow) * K + ac0 * 8;
    const __half* Bg = Bm + (size_t)(bn + tid) * K;
    uint32_t adst[4], bdst[8];
#pragma unroll
    for (int c = 0; c < 4; c++) adst[c] = GSW(arow * 128 + (ac0 + c) * 16);
#pragma unroll
    for (int c = 0; c < 8; c++) bdst[c] = 16384 + GSW(tid * 128 + c * 16);

    const uint32_t aRow = wm + (lane & 7) + ((lane >> 3) & 1) * 8;
    const uint32_t aKb  = ((lane >> 4) & 1) * 16;
    const uint32_t bRow = wn + (lane & 7) + ((lane >> 4) & 1) * 8;
    const uint32_t bKb  = ((lane >> 3) & 1) * 16;

    float acc[4][8][4];
#pragma unroll
    for (int i = 0; i < 4; i++)
#pragma unroll
        for (int j = 0; j < 8; j++)
#pragma unroll
            for (int r = 0; r < 4; r++) acc[i][j][r] = 0.0f;

    constexpr int NT = K / 64;
#pragma unroll
    for (int c = 0; c < 4; c++) cp16(smem + adst[c], Ag + c * 8);
#pragma unroll
    for (int c = 0; c < 8; c++) cp16(smem + bdst[c], Bg + c * 8);
    asm volatile("cp.async.commit_group;");

#pragma unroll 2
    for (int t = 0; t < NT; t++) {
        asm volatile("cp.async.wait_group 0;");
        __syncthreads();
        if (t + 1 < NT) {
            char* sd = smem + ((t + 1) & 1) * GPSTG;
            const int k0 = (t + 1) * 64;
#pragma unroll
            for (int c = 0; c < 4; c++) cp16(sd + adst[c], Ag + k0 + c * 8);
#pragma unroll
            for (int c = 0; c < 8; c++) cp16(sd + bdst[c], Bg + k0 + c * 8);
            asm volatile("cp.async.commit_group;");
        }

        const uint32_t sA = sb + (t & 1) * GPSTG;
        const uint32_t sB = sA + 16384;
#pragma unroll
        for (int ks = 0; ks < 4; ks++) {
            uint32_t af[4][4], bf[4][4];
#pragma unroll
            for (int im = 0; im < 4; im++)
                ldsm4(af[im], sA + GSW((aRow + im * 16) * 128 + ks * 32 + aKb));
#pragma unroll
            for (int jp = 0; jp < 4; jp++)
                ldsm4(bf[jp], sB + GSW((bRow + jp * 16) * 128 + ks * 32 + bKb));
#pragma unroll
            for (int im = 0; im < 4; im++)
#pragma unroll
                for (int jn = 0; jn < 8; jn++) {
                    const uint32_t* bb = bf[jn >> 1];
                    const int sx = (jn & 1) * 2;
                    mma_f16(acc[im][jn], af[im], bb[sx], bb[sx + 1]);
                }
        }
    }

    const int er = lane >> 2, ec = 2 * (lane & 3);
#pragma unroll
    for (int im = 0; im < 4; im++)
#pragma unroll
        for (int jn = 0; jn < 8; jn++) {
            const int row = bm + wm + im * 16 + er;
            const int col = bn + wn + jn * 8 + ec;
            *(__half2*)&C[(size_t)row * N + col] =
                __floats2half2_rn(acc[im][jn][0], acc[im][jn][1]);
            *(__half2*)&C[(size_t)(row + 8) * N + col] =
                __floats2half2_rn(acc[im][jn][2], acc[im][jn][3]);
        }
}

// ---------------- fp16 GEMM: CTA 128x128, K-tile 64, 8 warps 2x4, 2-stage ----------------
#define GSTG 32768
#define GS_SMEM (2 * GSTG)

template<int K, int OUTHALF>
__global__ __launch_bounds__(256, 2) void gemm_h(
    const __half* __restrict__ A, const __half* __restrict__ Bm,
    void* __restrict__ Cv, int M, int N)
{
    extern __shared__ char smem[];
    const uint32_t sb = smem_u32(smem);
    const int tid = threadIdx.x, lane = tid & 31, wid = tid >> 5;
    const int bm = blockIdx.y * 128, bn = blockIdx.x * 128;
    const int wm = (wid & 1) * 64, wn = (wid >> 1) * 32;

    const int lrow = tid >> 1, lc0 = (tid & 1) * 4;
    const __half* Ag = A + (size_t)(bm + lrow) * K + lc0 * 8;
    const __half* Bg = Bm + (size_t)(bn + lrow) * K + lc0 * 8;
    uint32_t sdst[4];
#pragma unroll
    for (int c = 0; c < 4; c++) sdst[c] = GSW(lrow * 128 + (lc0 + c) * 16);

    const uint32_t aRow = wm + (lane & 7) + ((lane >> 3) & 1) * 8;
    const uint32_t aKb  = ((lane >> 4) & 1) * 16;
    const uint32_t bRow = wn + (lane & 7) + ((lane >> 4) & 1) * 8;
    const uint32_t bKb  = ((lane >> 3) & 1) * 16;

    float acc[4][4][4];
#pragma unroll
    for (int i = 0; i < 4; i++)
#pragma unroll
        for (int j = 0; j < 4; j++)
#pragma unroll
            for (int r = 0; r < 4; r++) acc[i][j][r] = 0.0f;

    constexpr int NT = K / 64;
#pragma unroll
    for (int c = 0; c < 4; c++) {
        cp16(smem + sdst[c], Ag + c * 8);
        cp16(smem + 16384 + sdst[c], Bg + c * 8);
    }
    asm volatile("cp.async.commit_group;");

#pragma unroll 4
    for (int t = 0; t < NT; t++) {
        asm volatile("cp.async.wait_group 0;");
        __syncthreads();
        if (t + 1 < NT) {
            char* sd = smem + ((t + 1) & 1) * GSTG;
            const int k0 = (t + 1) * 64;
#pragma unroll
            for (int c = 0; c < 4; c++) {
                cp16(sd + sdst[c], Ag + k0 + c * 8);
                cp16(sd + 16384 + sdst[c], Bg + k0 + c * 8);
            }
            asm volatile("cp.async.commit_group;");
        }

        const uint32_t sA = sb + (t & 1) * GSTG;
        const uint32_t sB = sA + 16384;
#pragma unroll
        for (int ks = 0; ks < 4; ks++) {
            uint32_t af[4][4], bf[2][4];
#pragma unroll
            for (int im = 0; im < 4; im++)
                ldsm4(af[im], sA + GSW((aRow + im * 16) * 128 + ks * 32 + aKb));
#pragma unroll
            for (int jp = 0; jp < 2; jp++)
                ldsm4(bf[jp], sB + GSW((bRow + jp * 16) * 128 + ks * 32 + bKb));
#pragma unroll
            for (int im = 0; im < 4; im++)
#pragma unroll
                for (int jn = 0; jn < 4; jn++) {
                    const uint32_t* bb = bf[jn >> 1];
                    const int sx = (jn & 1) * 2;
                    mma_f16(acc[im][jn], af[im], bb[sx], bb[sx + 1]);
                }
        }
    }

    const int er = lane >> 2, ec = 2 * (lane & 3);
#pragma unroll
    for (int im = 0; im < 4; im++)
#pragma unroll
        for (int jn = 0; jn < 4; jn++) {
            const int row = bm + wm + im * 16 + er;
            const int col = bn + wn + jn * 8 + ec;
            if (OUTHALF) {
                __half* C = (__half*)Cv;
                *(__half2*)&C[(size_t)row * N + col] =
                    __floats2half2_rn(acc[im][jn][0], acc[im][jn][1]);
                *(__half2*)&C[(size_t)(row + 8) * N + col] =
                    __floats2half2_rn(acc[im][jn][2], acc[im][jn][3]);
            } else {
                float* C = (float*)Cv;
                *(float2*)&C[(size_t)row * N + col] =
                    make_float2(acc[im][jn][0], acc[im][jn][1]);
                *(float2*)&C[(size_t)(row + 8) * N + col] =
                    make_float2(acc[im][jn][2], acc[im][jn][3]);
            }
        }
}

// ---------------- single-branch flash attention, atomic mix epilogue ----------------
// grid: (L/128, NH, 2*B). z = branch*B + b. CTA: 128 q, 8 warps x 16 rows. 3-stage.
#define ASTG 16384                  // K 8KB + V 8KB
#define ATTN_SMEM (3 * ASTG)        // 49152

__global__ __launch_bounds__(256, 2) void attn_h(
    const __half* __restrict__ Proj, __half* __restrict__ Mix,
    const float* __restrict__ p_mixw, const float* __restrict__ p_decay)
{
    extern __shared__ char smem[];
    const uint32_t sb = smem_u32(smem);
    const int tid = threadIdx.x, lane = tid & 31, wid = tid >> 5;
    const int g = lane >> 2, tg = lane & 3;
    const int q0 = blockIdx.x * 128;
    const int h = blockIdx.y;
    const int branch = blockIdx.z / B_, b = blockIdx.z % B_;
    const int mw = wid * 16;

    const float lambda2 = (1.0f - p_decay[0]) * LOG2E;
    const float aw = 1.0f / (1.0f + __expf(-p_mixw[0]));
    const float wmix = branch ? (1.0f - aw) : aw;

    const uint32_t bRow = (lane & 7) + ((lane >> 4) & 1) * 8;   // K frags: key row
    const uint32_t bKb  = ((lane >> 3) & 1) * 16;
    const uint32_t vRow = (lane & 7) + ((lane >> 3) & 1) * 8;   // V trans: key row
    const uint32_t vKb  = ((lane >> 4) & 1) * 16;

    // Q fragments (pre-scaled via folded weights)
    uint32_t qa[4][4];
    {
        const __half* r0 = Proj + ((size_t)(b * L_ + q0 + mw + g)) * NP_ + h * HD_;
        const __half* r1 = r0 + (size_t)8 * NP_;
#pragma unroll
        for (int ks = 0; ks < 4; ks++) {
            qa[ks][0] = *(const uint32_t*)(r0 + ks * 16 + 2 * tg);
            qa[ks][1] = *(const uint32_t*)(r1 + ks * 16 + 2 * tg);
            qa[ks][2] = *(const uint32_t*)(r0 + ks * 16 + 8 + 2 * tg);
            qa[ks][3] = *(const uint32_t*)(r1 + ks * 16 + 8 + 2 * tg);
        }
    }

    const int kr = tid >> 2, c0 = tid & 3;
    const int kvOff = H_ + branch * 2 * H_;

    auto issue_load = [&](int tt) {
        const __half* Kb = Proj + ((size_t)(b * L_ + tt * 64 + kr)) * NP_ + kvOff + h * HD_;
        const __half* Vb = Kb + H_;
        char* stg = smem + (tt % 3) * ASTG;
#pragma unroll
        for (int c = 0; c < 2; c++) {
            const int ch = c0 + c * 4;
            const uint32_t d = GSW(kr * 128 + ch * 16);
            cp16(stg + d, Kb + ch * 8);
            cp16(stg + 8192 + d, Vb + ch * 8);
        }
        asm volatile("cp.async.commit_group;");
    };

    issue_load(0);
    issue_load(1);

    float l0 = 0.0f, l1 = 0.0f;
    float o[8][4];
#pragma unroll
    for (int jn = 0; jn < 8; jn++)
#pragma unroll
        for (int r = 0; r < 4; r++) o[jn][r] = 0.0f;

    for (int t = 0; t < 16; t++) {
        asm volatile("cp.async.wait_group 1;");
        __syncthreads();
        if (t + 2 < 16) issue_load(t + 2);

        const uint32_t stK = sb + (t % 3) * ASTG;
        const uint32_t stV = stK + 8192;

        // ---- S = Q K^T ----
        float s[8][4];
#pragma unroll
        for (int jn = 0; jn < 8; jn++)
#pragma unroll
            for (int r = 0; r < 4; r++) s[jn][r] = 0.0f;
#pragma unroll
        for (int ks = 0; ks < 4; ks++) {
            uint32_t bf[4][4];
#pragma unroll
            for (int jp = 0; jp < 4; jp++)
                ldsm4(bf[jp], stK + GSW((bRow + jp * 16) * 128 + ks * 32 + bKb));
#pragma unroll
            for (int jn = 0; jn < 8; jn++) {
                const uint32_t* bb = bf[jn >> 1];
                const int sx = (jn & 1) * 2;
                mma_f16(s[jn], qa[ks], bb[sx], bb[sx + 1]);
            }
        }

        if (branch == 0) {
            const float r0 = (float)(q0 + mw + g), r1 = r0 + 8.0f;
#pragma unroll
            for (int jn = 0; jn < 8; jn++) {
                const float cA = (float)(t * 64 + jn * 8 + 2 * tg), cB = cA + 1.0f;
                s[jn][0] -= fabsf(r0 - cA) * lambda2;
                s[jn][1] -= fabsf(r0 - cB) * lambda2;
                s[jn][2] -= fabsf(r1 - cA) * lambda2;
                s[jn][3] -= fabsf(r1 - cB) * lambda2;
            }
        }

        // ---- p = exp2(s - 12): stays in registers as PV A-fragments ----
        uint32_t pf[4][4];
#pragma unroll
        for (int jn = 0; jn < 8; jn++) {
            const float p0 = ex2(s[jn][0] - 12.0f);
            const float p1 = ex2(s[jn][1] - 12.0f);
            const float p2 = ex2(s[jn][2] - 12.0f);
            const float p3 = ex2(s[jn][3] - 12.0f);
            l0 += p0 + p1; l1 += p2 + p3;
            const int kc = jn >> 1, half = (jn & 1) * 2;
            pf[kc][half + 0] = packh2(p0, p1);
            pf[kc][half + 1] = packh2(p2, p3);
        }

        // ---- O += P V ----
#pragma unroll
        for (int ks = 0; ks < 4; ks++) {
            uint32_t vf[4][4];
#pragma unroll
            for (int jp = 0; jp < 4; jp++)
                ldsm4t(vf[jp], stV + GSW((ks * 16 + vRow) * 128 + jp * 32 + vKb));
#pragma unroll
            for (int jn = 0; jn < 8; jn++) {
                const uint32_t* bb = vf[jn >> 1];
                const int sx = (jn & 1) * 2;
                mma_f16(o[jn], pf[ks], bb[sx], bb[sx + 1]);
            }
        }
    }

    l0 += __shfl_xor_sync(0xffffffffu, l0, 1);
    l0 += __shfl_xor_sync(0xffffffffu, l0, 2);
    l1 += __shfl_xor_sync(0xffffffffu, l1, 1);
    l1 += __shfl_xor_sync(0xffffffffu, l1, 2);

    const float i0 = wmix / l0, i1 = wmix / l1;
    __half* ob = Mix + ((size_t)(b * L_ + q0 + mw + g)) * H_ + h * HD_;
#pragma unroll
    for (int jn = 0; jn < 8; jn++) {
        const int col = jn * 8 + 2 * tg;
        red_h2(ob + col, packh2(o[jn][0] * i0, o[jn][1] * i0));
        red_h2(ob + 8 * H_ + col, packh2(o[jn][2] * i1, o[jn][3] * i1));
    }
}

// ---------------------------------------------------------------------------
extern "C" void kernel_launch(void* const* d_in, const int* in_sizes, int n_in,
                              void* d_out, int out_size)
{
    const float* x     = (const float*)d_in[0];
    const float* Wq    = (const float*)d_in[1];
    const float* Wkvs  = (const float*)d_in[2];
    const float* Wkvl  = (const float*)d_in[3];
    const float* Wo    = (const float*)d_in[4];
    const float* mixw  = (const float*)d_in[5];
    const float* decay = (const float*)d_in[6];
    float* out = (float*)d_out;

    __half *xh, *proj, *mixh, *wall, *woth;
    cudaGetSymbolAddress((void**)&xh,   g_xh);
    cudaGetSymbolAddress((void**)&proj, g_proj);
    cudaGetSymbolAddress((void**)&mixh, g_mixh);
    cudaGetSymbolAddress((void**)&wall, g_Wall);
    cudaGetSymbolAddress((void**)&woth, g_Woth);

    cudaFuncSetAttribute(gemm_p<1024>,
                         cudaFuncAttributeMaxDynamicSharedMemorySize, GP_SMEM);
    cudaFuncSetAttribute(gemm_h<1024, 0>,
                         cudaFuncAttributeMaxDynamicSharedMemorySize, GS_SMEM);
    cudaFuncSetAttribute(attn_h,
                         cudaFuncAttributeMaxDynamicSharedMemorySize, ATTN_SMEM);

    // preprocess
    to_half<<<M_ * H_ / 4 / 256, 256>>>(x, xh, M_ * H_ / 4);
    wtrans_h<<<dim3(2 * H_ / 32, H_ / 32, 4), dim3(32, 8)>>>(Wq, Wkvs, Wkvl, Wo,
                                                             wall, woth);
    zero_h<<<M_ * H_ / 8 / 256, 256>>>((float4*)mixh, M_ * H_ / 8);

    // fused projections: proj[M, 5120], 128x256 CTA / 64x64 warp tiles
    gemm_p<1024><<<dim3(NP_ / 256, M_ / 128), 256, GP_SMEM>>>(xh, wall, proj, M_, NP_);

    // attention: one branch per CTA; atomic-mix into Mix[M, H]
    attn_h<<<dim3(L_ / 128, NH_, 2 * B_), 256, ATTN_SMEM>>>(proj, mixh, mixw, decay);

    // output projection (fp32 out)
    gemm_h<1024, 0><<<dim3(H_ / 128, M_ / 128), 256, GS_SMEM>>>(mixh, woth, out, M_, H_);
}

// round 17
// speedup vs baseline: 1.2211x; 1.2211x over previous
#include <cuda_runtime.h>
#include <cuda_fp16.h>
#include <cstdint>

#define B_  4
#define L_  1024
#define H_  1024
#define NH_ 16
#define HD_ 64
#define M_  (B_*L_)   // 4096
#define NP_ (5 * H_)  // fused projection width 5120
#define LOG2E 1.4426950408889634f

// ---------------- scratch ----------------
__device__ __half g_xh  [M_ * H_];
__device__ __half g_proj[M_ * NP_];          // [Q(scaled) | Ks | Vs | Kl | Vl]
__device__ __half g_mixh[M_ * H_];           // atomically mixed attention output
__device__ __half g_Wall[NP_ * H_];          // [Wq^T*qs ; Wkvs^T ; Wkvl^T]
__device__ __half g_Woth[H_ * H_];           // Wo^T

// ---------------- PTX helpers ----------------
__device__ __forceinline__ float ex2(float x) {
    float y; asm("ex2.approx.ftz.f32 %0, %1;" : "=f"(y) : "f"(x)); return y;
}
__device__ __forceinline__ void mma_f16(float* d, const uint32_t* a,
                                        uint32_t b0, uint32_t b1) {
    asm volatile(
        "mma.sync.aligned.m16n8k16.row.col.f32.f16.f16.f32 "
        "{%0,%1,%2,%3}, {%4,%5,%6,%7}, {%8,%9}, {%0,%1,%2,%3};"
        : "+f"(d[0]), "+f"(d[1]), "+f"(d[2]), "+f"(d[3])
        : "r"(a[0]), "r"(a[1]), "r"(a[2]), "r"(a[3]), "r"(b0), "r"(b1));
}
__device__ __forceinline__ void ldsm4(uint32_t* r, uint32_t addr) {
    asm volatile("ldmatrix.sync.aligned.m8n8.x4.shared.b16 {%0,%1,%2,%3}, [%4];"
        : "=r"(r[0]), "=r"(r[1]), "=r"(r[2]), "=r"(r[3]) : "r"(addr));
}
__device__ __forceinline__ void ldsm4t(uint32_t* r, uint32_t addr) {
    asm volatile("ldmatrix.sync.aligned.m8n8.x4.trans.shared.b16 {%0,%1,%2,%3}, [%4];"
        : "=r"(r[0]), "=r"(r[1]), "=r"(r[2]), "=r"(r[3]) : "r"(addr));
}
__device__ __forceinline__ void cp16(void* smem_dst, const void* gmem_src) {
    unsigned s = (unsigned)__cvta_generic_to_shared(smem_dst);
    asm volatile("cp.async.cg.shared.global [%0], [%1], 16;" :: "r"(s), "l"(gmem_src));
}
__device__ __forceinline__ uint32_t smem_u32(const void* p) {
    uint32_t a;
    asm("{ .reg .u64 t; cvta.to.shared.u64 t, %1; cvt.u32.u64 %0, t; }" : "=r"(a) : "l"(p));
    return a;
}
__device__ __forceinline__ uint32_t packh2(float a, float b) {
    uint32_t r;
    asm("cvt.rn.f16x2.f32 %0, %2, %1;" : "=r"(r) : "f"(a), "f"(b));
    return r;
}
__device__ __forceinline__ void red_h2(__half* p, uint32_t v) {
    asm volatile("red.global.add.noftz.f16x2 [%0], %1;" :: "l"(p), "r"(v) : "memory");
}
#define GSW(o) ((o) ^ (((o) >> 3) & 0x70))

// ---------------- fused preprocessing: one launch ----------------
// grid (64, 32, 6), block (32, 8):
//   z=0..3: weight transpose+round (Wq*qscale, Wkvs, Wkvl -> Wall; Wo -> Woth)
//   z=4   : x fp32 -> half
//   z=5   : zero Mix
__global__ __launch_bounds__(256) void prep_all(
    const float* __restrict__ x,
    const float* __restrict__ Wq, const float* __restrict__ Ws,
    const float* __restrict__ Wl, const float* __restrict__ Wo,
    __half* __restrict__ xh, __half* __restrict__ Wall,
    __half* __restrict__ Woth, __half* __restrict__ Mix)
{
    const int z = blockIdx.z;
    const int tx = threadIdx.x, ty = threadIdx.y;

    if (z == 4) {
        // x -> half: 2048 flat blocks x 256 threads x 2 float4
        const int fb = blockIdx.y * 64 + blockIdx.x;
        const int tflat = ty * 32 + tx;
#pragma unroll
        for (int it = 0; it < 2; it++) {
            const int i = fb * 512 + it * 256 + tflat;   // < 1M float4
            float4 v = ((const float4*)x)[i];
            ((__half2*)xh)[2 * i]     = __floats2half2_rn(v.x, v.y);
            ((__half2*)xh)[2 * i + 1] = __floats2half2_rn(v.z, v.w);
        }
        return;
    }
    if (z == 5) {
        // zero Mix: 512K float4
        const int fb = blockIdx.y * 64 + blockIdx.x;
        const int i = fb * 256 + ty * 32 + tx;
        ((float4*)Mix)[i] = make_float4(0.f, 0.f, 0.f, 0.f);
        return;
    }

    const float* W = (z == 0) ? Wq : (z == 1) ? Ws : (z == 2) ? Wl : Wo;
    const int N = (z == 1 || z == 2) ? 2 * H_ : H_;
    const int n0 = blockIdx.x * 32, k0 = blockIdx.y * 32;
    if (n0 >= N) return;
    __shared__ float ts[32][33];
#pragma unroll
    for (int i = 0; i < 4; i++)
        ts[ty + 8 * i][tx] = W[(size_t)(k0 + ty + 8 * i) * N + n0 + tx];
    __syncthreads();
    const int rowOff = (z == 0) ? 0 : (z == 1) ? H_ : (z == 2) ? 3 * H_ : 0;
    const float sc = (z == 0) ? 0.125f * LOG2E : 1.0f;
    __half* T = (z == 3) ? Woth : (Wall + (size_t)rowOff * H_);
#pragma unroll
    for (int i = 0; i < 4; i++)
        T[(size_t)(n0 + ty + 8 * i) * H_ + k0 + tx] =
            __float2half_rn(ts[tx][ty + 8 * i] * sc);
}

// ---------------- fp16 GEMM: CTA 128x128, K-tile 64, 8 warps 2x4, 2-stage ----------------
#define GSTG 32768
#define GS_SMEM (2 * GSTG)

template<int K, int OUTHALF>
__global__ __launch_bounds__(256, 2) void gemm_h(
    const __half* __restrict__ A, const __half* __restrict__ Bm,
    void* __restrict__ Cv, int M, int N)
{
    extern __shared__ char smem[];
    const uint32_t sb = smem_u32(smem);
    const int tid = threadIdx.x, lane = tid & 31, wid = tid >> 5;
    const int bm = blockIdx.y * 128, bn = blockIdx.x * 128;
    const int wm = (wid & 1) * 64, wn = (wid >> 1) * 32;

    const int lrow = tid >> 1, lc0 = (tid & 1) * 4;
    const __half* Ag = A + (size_t)(bm + lrow) * K + lc0 * 8;
    const __half* Bg = Bm + (size_t)(bn + lrow) * K + lc0 * 8;
    uint32_t sdst[4];
#pragma unroll
    for (int c = 0; c < 4; c++) sdst[c] = GSW(lrow * 128 + (lc0 + c) * 16);

    const uint32_t aRow = wm + (lane & 7) + ((lane >> 3) & 1) * 8;
    const uint32_t aKb  = ((lane >> 4) & 1) * 16;
    const uint32_t bRow = wn + (lane & 7) + ((lane >> 4) & 1) * 8;
    const uint32_t bKb  = ((lane >> 3) & 1) * 16;

    float acc[4][4][4];
#pragma unroll
    for (int i = 0; i < 4; i++)
#pragma unroll
        for (int j = 0; j < 4; j++)
#pragma unroll
            for (int r = 0; r < 4; r++) acc[i][j][r] = 0.0f;

    constexpr int NT = K / 64;
#pragma unroll
    for (int c = 0; c < 4; c++) {
        cp16(smem + sdst[c], Ag + c * 8);
        cp16(smem + 16384 + sdst[c], Bg + c * 8);
    }
    asm volatile("cp.async.commit_group;");

#pragma unroll 4
    for (int t = 0; t < NT; t++) {
        asm volatile("cp.async.wait_group 0;");
        __syncthreads();
        if (t + 1 < NT) {
            char* sd = smem + ((t + 1) & 1) * GSTG;
            const int k0 = (t + 1) * 64;
#pragma unroll
            for (int c = 0; c < 4; c++) {
                cp16(sd + sdst[c], Ag + k0 + c * 8);
                cp16(sd + 16384 + sdst[c], Bg + k0 + c * 8);
            }
            asm volatile("cp.async.commit_group;");
        }

        const uint32_t sA = sb + (t & 1) * GSTG;
        const uint32_t sB = sA + 16384;
#pragma unroll
        for (int ks = 0; ks < 4; ks++) {
            uint32_t af[4][4], bf[2][4];
#pragma unroll
            for (int im = 0; im < 4; im++)
                ldsm4(af[im], sA + GSW((aRow + im * 16) * 128 + ks * 32 + aKb));
#pragma unroll
            for (int jp = 0; jp < 2; jp++)
                ldsm4(bf[jp], sB + GSW((bRow + jp * 16) * 128 + ks * 32 + bKb));
#pragma unroll
            for (int im = 0; im < 4; im++)
#pragma unroll
                for (int jn = 0; jn < 4; jn++) {
                    const uint32_t* bb = bf[jn >> 1];
                    const int sx = (jn & 1) * 2;
                    mma_f16(acc[im][jn], af[im], bb[sx], bb[sx + 1]);
                }
        }
    }

    const int er = lane >> 2, ec = 2 * (lane & 3);
#pragma unroll
    for (int im = 0; im < 4; im++)
#pragma unroll
        for (int jn = 0; jn < 4; jn++) {
            const int row = bm + wm + im * 16 + er;
            const int col = bn + wn + jn * 8 + ec;
            if (OUTHALF) {
                __half* C = (__half*)Cv;
                *(__half2*)&C[(size_t)row * N + col] =
                    __floats2half2_rn(acc[im][jn][0], acc[im][jn][1]);
                *(__half2*)&C[(size_t)(row + 8) * N + col] =
                    __floats2half2_rn(acc[im][jn][2], acc[im][jn][3]);
            } else {
                float* C = (float*)Cv;
                *(float2*)&C[(size_t)row * N + col] =
                    make_float2(acc[im][jn][0], acc[im][jn][1]);
                *(float2*)&C[(size_t)(row + 8) * N + col] =
                    make_float2(acc[im][jn][2], acc[im][jn][3]);
            }
        }
}

// ---------------- single-branch flash attention, atomic mix epilogue ----------------
// grid: (L/128, NH, 2*B). z = branch*B + b. CTA: 128 q, 8 warps x 16 rows. 3-stage.
#define ASTG 16384                  // K 8KB + V 8KB
#define ATTN_SMEM (3 * ASTG)        // 49152

__global__ __launch_bounds__(256, 2) void attn_h(
    const __half* __restrict__ Proj, __half* __restrict__ Mix,
    const float* __restrict__ p_mixw, const float* __restrict__ p_decay)
{
    extern __shared__ char smem[];
    const uint32_t sb = smem_u32(smem);
    const int tid = threadIdx.x, lane = tid & 31, wid = tid >> 5;
    const int g = lane >> 2, tg = lane & 3;
    const int q0 = blockIdx.x * 128;
    const int h = blockIdx.y;
    const int branch = blockIdx.z / B_, b = blockIdx.z % B_;
    const int mw = wid * 16;

    const float lambda2 = (1.0f - p_decay[0]) * LOG2E;
    const float aw = 1.0f / (1.0f + __expf(-p_mixw[0]));
    const float wmix = branch ? (1.0f - aw) : aw;

    const uint32_t bRow = (lane & 7) + ((lane >> 4) & 1) * 8;   // K frags: key row
    const uint32_t bKb  = ((lane >> 3) & 1) * 16;
    const uint32_t vRow = (lane & 7) + ((lane >> 3) & 1) * 8;   // V trans: key row
    const uint32_t vKb  = ((lane >> 4) & 1) * 16;

    // Q fragments (pre-scaled via folded weights)
    uint32_t qa[4][4];
    {
        const __half* r0 = Proj + ((size_t)(b * L_ + q0 + mw + g)) * NP_ + h * HD_;
        const __half* r1 = r0 + (size_t)8 * NP_;
#pragma unroll
        for (int ks = 0; ks < 4; ks++) {
            qa[ks][0] = *(const uint32_t*)(r0 + ks * 16 + 2 * tg);
            qa[ks][1] = *(const uint32_t*)(r1 + ks * 16 + 2 * tg);
            qa[ks][2] = *(const uint32_t*)(r0 + ks * 16 + 8 + 2 * tg);
            qa[ks][3] = *(const uint32_t*)(r1 + ks * 16 + 8 + 2 * tg);
        }
    }

    const int kr = tid >> 2, c0 = tid & 3;
    const int kvOff = H_ + branch * 2 * H_;

    auto issue_load = [&](int tt) {
        const __half* Kb = Proj + ((size_t)(b * L_ + tt * 64 + kr)) * NP_ + kvOff + h * HD_;
        const __half* Vb = Kb + H_;
        char* stg = smem + (tt % 3) * ASTG;
#pragma unroll
        for (int c = 0; c < 2; c++) {
            const int ch = c0 + c * 4;
            const uint32_t d = GSW(kr * 128 + ch * 16);
            cp16(stg + d, Kb + ch * 8);
            cp16(stg + 8192 + d, Vb + ch * 8);
        }
        asm volatile("cp.async.commit_group;");
    };

    issue_load(0);
    issue_load(1);

    float l0 = 0.0f, l1 = 0.0f;
    float o[8][4];
#pragma unroll
    for (int jn = 0; jn < 8; jn++)
#pragma unroll
        for (int r = 0; r < 4; r++) o[jn][r] = 0.0f;

    for (int t = 0; t < 16; t++) {
        asm volatile("cp.async.wait_group 1;");
        __syncthreads();
        if (t + 2 < 16) issue_load(t + 2);

        const uint32_t stK = sb + (t % 3) * ASTG;
        const uint32_t stV = stK + 8192;

        // ---- S = Q K^T ----
        float s[8][4];
#pragma unroll
        for (int jn = 0; jn < 8; jn++)
#pragma unroll
            for (int r = 0; r < 4; r++) s[jn][r] = 0.0f;
#pragma unroll
        for (int ks = 0; ks < 4; ks++) {
            uint32_t bf[4][4];
#pragma unroll
            for (int jp = 0; jp < 4; jp++)
                ldsm4(bf[jp], stK + GSW((bRow + jp * 16) * 128 + ks * 32 + bKb));
#pragma unroll
            for (int jn = 0; jn < 8; jn++) {
                const uint32_t* bb = bf[jn >> 1];
                const int sx = (jn & 1) * 2;
                mma_f16(s[jn], qa[ks], bb[sx], bb[sx + 1]);
            }
        }

        if (branch == 0) {
            const float r0 = (float)(q0 + mw + g), r1 = r0 + 8.0f;
#pragma unroll
            for (int jn = 0; jn < 8; jn++) {
                const float cA = (float)(t * 64 + jn * 8 + 2 * tg), cB = cA + 1.0f;
                s[jn][0] -= fabsf(r0 - cA) * lambda2;
                s[jn][1] -= fabsf(r0 - cB) * lambda2;
                s[jn][2] -= fabsf(r1 - cA) * lambda2;
                s[jn][3] -= fabsf(r1 - cB) * lambda2;
            }
        }

        // ---- p = exp2(s - 12): stays in registers as PV A-fragments ----
        uint32_t pf[4][4];
#pragma unroll
        for (int jn = 0; jn < 8; jn++) {
            const float p0 = ex2(s[jn][0] - 12.0f);
            const float p1 = ex2(s[jn][1] - 12.0f);
            const float p2 = ex2(s[jn][2] - 12.0f);
            const float p3 = ex2(s[jn][3] - 12.0f);
            l0 += p0 + p1; l1 += p2 + p3;
            const int kc = jn >> 1, half = (jn & 1) * 2;
            pf[kc][half + 0] = packh2(p0, p1);
            pf[kc][half + 1] = packh2(p2, p3);
        }

        // ---- O += P V ----
#pragma unroll
        for (int ks = 0; ks < 4; ks++) {
            uint32_t vf[4][4];
#pragma unroll
            for (int jp = 0; jp < 4; jp++)
                ldsm4t(vf[jp], stV + GSW((ks * 16 + vRow) * 128 + jp * 32 + vKb));
#pragma unroll
            for (int jn = 0; jn < 8; jn++) {
                const uint32_t* bb = vf[jn >> 1];
                const int sx = (jn & 1) * 2;
                mma_f16(o[jn], pf[ks], bb[sx], bb[sx + 1]);
            }
        }
    }

    l0 += __shfl_xor_sync(0xffffffffu, l0, 1);
    l0 += __shfl_xor_sync(0xffffffffu, l0, 2);
    l1 += __shfl_xor_sync(0xffffffffu, l1, 1);
    l1 += __shfl_xor_sync(0xffffffffu, l1, 2);

    const float i0 = wmix / l0, i1 = wmix / l1;
    __half* ob = Mix + ((size_t)(b * L_ + q0 + mw + g)) * H_ + h * HD_;
#pragma unroll
    for (int jn = 0; jn < 8; jn++) {
        const int col = jn * 8 + 2 * tg;
        red_h2(ob + col, packh2(o[jn][0] * i0, o[jn][1] * i0));
        red_h2(ob + 8 * H_ + col, packh2(o[jn][2] * i1, o[jn][3] * i1));
    }
}

// ---------------------------------------------------------------------------
extern "C" void kernel_launch(void* const* d_in, const int* in_sizes, int n_in,
                              void* d_out, int out_size)
{
    const float* x     = (const float*)d_in[0];
    const float* Wq    = (const float*)d_in[1];
    const float* Wkvs  = (const float*)d_in[2];
    const float* Wkvl  = (const float*)d_in[3];
    const float* Wo    = (const float*)d_in[4];
    const float* mixw  = (const float*)d_in[5];
    const float* decay = (const float*)d_in[6];
    float* out = (float*)d_out;

    __half *xh, *proj, *mixh, *wall, *woth;
    cudaGetSymbolAddress((void**)&xh,   g_xh);
    cudaGetSymbolAddress((void**)&proj, g_proj);
    cudaGetSymbolAddress((void**)&mixh, g_mixh);
    cudaGetSymbolAddress((void**)&wall, g_Wall);
    cudaGetSymbolAddress((void**)&woth, g_Woth);

    cudaFuncSetAttribute(gemm_h<1024, 1>,
                         cudaFuncAttributeMaxDynamicSharedMemorySize, GS_SMEM);
    cudaFuncSetAttribute(gemm_h<1024, 0>,
                         cudaFuncAttributeMaxDynamicSharedMemorySize, GS_SMEM);
    cudaFuncSetAttribute(attn_h,
                         cudaFuncAttributeMaxDynamicSharedMemorySize, ATTN_SMEM);

    // fused preprocess: weights + x->half + zero mix, one launch
    prep_all<<<dim3(64, 32, 6), dim3(32, 8)>>>(x, Wq, Wkvs, Wkvl, Wo,
                                               xh, wall, woth, mixh);

    // fused projections: proj[M, 5120]
    gemm_h<1024, 1><<<dim3(NP_ / 128, M_ / 128), 256, GS_SMEM>>>(xh, wall, proj, M_, NP_);

    // attention: one branch per CTA; atomic-mix into Mix[M, H]
    attn_h<<<dim3(L_ / 128, NH_, 2 * B_), 256, ATTN_SMEM>>>(proj, mixh, mixw, decay);

    // output projection (fp32 out)
    gemm_h<1024, 0><<<dim3(H_ / 128, M_ / 128), 256, GS_SMEM>>>(mixh, woth, out, M_, H_);
}